// round 4
// baseline (speedup 1.0000x reference)
#include <cuda_runtime.h>
#include <cuda_fp16.h>
#include <cstdint>

#define BZ 32
#define CH 64
#define HH 128
#define WW 128
#define TILE_H 4
#define TILE_W 32
#define MP_STRIDE 136   // words per c2-row (128 px + 8 pad): conflict-free STS & mma LDS
#define WP_STRIDE 33    // words per o-row of packed weights
#define DS_STRIDE 68    // words per o-row of staged y (64 px-pairs + 4 pad): conflict-free

// 67 MB fp16 scratch for y = conv1x1(boxmean(x)), layout [b][c][h][w]
__device__ __half y_scratch[(size_t)BZ * CH * HH * WW];

// ---------------- K1: box mean + channel GEMM -> y (fp16) ----------------
__global__ __launch_bounds__(256, 4)
void k1_mean_gemm(const float* __restrict__ x,
                  const float* __restrict__ conv_w) {
    __shared__ uint32_t Mp[32 * MP_STRIDE];     // 17408 B  fp16x2 means [c2][px]
    __shared__ uint32_t Wp[64 * WP_STRIDE];     //  8448 B  fp16x2 weights [o][c2]
    __shared__ uint32_t DsmW[64 * DS_STRIDE];   // 17408 B  fp16x2 y [o][px-pair]

    const int tid  = threadIdx.x;
    const int warp = tid >> 5;
    const int lane = tid & 31;

    const int b  = blockIdx.z;
    const int h0 = blockIdx.y * TILE_H;
    const int w0 = blockIdx.x * TILE_W;

    // phase 0: stage weights fp16x2
    for (int i = tid; i < 64 * 32; i += 256) {
        const int o = i >> 5, c2 = i & 31;
        const float2 wv = reinterpret_cast<const float2*>(conv_w)[o * 32 + c2];
        __half2 pk = __floats2half2_rn(wv.x, wv.y);
        Wp[o * WP_STRIDE + c2] = *reinterpret_cast<uint32_t*>(&pk);
    }

    // phase 1: edge-clipped 3x3 box mean over 4x32 tile (6-row window)
    const float* xb = x + (size_t)b * CH * HH * WW;
    const int   w    = w0 + lane;
    const float invw = (w == 0 || w == WW - 1) ? 0.5f : (1.0f / 3.0f);

    #pragma unroll 1
    for (int chunk = 0; chunk < 4; chunk++) {
        const int ca = chunk * 16 + warp * 2;
        const float* pa  = xb + ca * (HH * WW);
        const float* pb2 = pa + (HH * WW);
        float hsA[6], hsB[6];
        #pragma unroll
        for (int i = 0; i < 6; i++) {
            const int r = h0 - 1 + i;
            const bool rin = (r >= 0) && (r < HH);
            float va = 0.f, vb = 0.f;
            if (rin) { va = pa[r * WW + w]; vb = pb2[r * WW + w]; }
            float la = __shfl_up_sync(0xffffffffu, va, 1);
            float lb = __shfl_up_sync(0xffffffffu, vb, 1);
            float ra = __shfl_down_sync(0xffffffffu, va, 1);
            float rb = __shfl_down_sync(0xffffffffu, vb, 1);
            if (lane == 0) {
                la = (rin && w0 > 0) ? pa[r * WW + w0 - 1]  : 0.f;
                lb = (rin && w0 > 0) ? pb2[r * WW + w0 - 1] : 0.f;
            }
            if (lane == 31) {
                ra = (rin && (w0 + TILE_W) < WW) ? pa[r * WW + w0 + TILE_W]  : 0.f;
                rb = (rin && (w0 + TILE_W) < WW) ? pb2[r * WW + w0 + TILE_W] : 0.f;
            }
            hsA[i] = la + va + ra;
            hsB[i] = lb + vb + rb;
        }
        #pragma unroll
        for (int ro = 0; ro < TILE_H; ro++) {
            const int h = h0 + ro;
            const float invh = (h == 0 || h == HH - 1) ? 0.5f : (1.0f / 3.0f);
            const float s = invh * invw;
            const float ma = (hsA[ro] + hsA[ro + 1] + hsA[ro + 2]) * s;
            const float mb = (hsB[ro] + hsB[ro + 1] + hsB[ro + 2]) * s;
            __half2 pk = __floats2half2_rn(ma, mb);
            Mp[(ca >> 1) * MP_STRIDE + ro * 32 + lane] =
                *reinterpret_cast<uint32_t*>(&pk);
        }
    }
    __syncthreads();

    // phase 2: D[o,p] = sum_c W[o,c]*mean[p,c];  M=64, N=128, K=64
    const int o0   = (warp >> 1) * 16;
    const int nsub = (warp & 1) * 64;
    const int lq = lane >> 2;
    const int lr = lane & 3;

    uint32_t a[4][4];
    #pragma unroll
    for (int kk = 0; kk < 4; kk++) {
        a[kk][0] = Wp[(o0 + lq)     * WP_STRIDE + kk * 8 + lr];
        a[kk][1] = Wp[(o0 + 8 + lq) * WP_STRIDE + kk * 8 + lr];
        a[kk][2] = Wp[(o0 + lq)     * WP_STRIDE + kk * 8 + 4 + lr];
        a[kk][3] = Wp[(o0 + 8 + lq) * WP_STRIDE + kk * 8 + 4 + lr];
    }
    const int oA = o0 + lq, oB = oA + 8;

    #pragma unroll
    for (int nt = 0; nt < 8; nt++) {
        const int n0 = nsub + nt * 8;
        float acc0 = 0.f, acc1 = 0.f, acc2 = 0.f, acc3 = 0.f;
        #pragma unroll
        for (int kk = 0; kk < 4; kk++) {
            const uint32_t b0 = Mp[(kk * 8 + lr)     * MP_STRIDE + n0 + lq];
            const uint32_t b1 = Mp[(kk * 8 + 4 + lr) * MP_STRIDE + n0 + lq];
            asm volatile(
                "mma.sync.aligned.m16n8k16.row.col.f32.f16.f16.f32 "
                "{%0,%1,%2,%3}, {%4,%5,%6,%7}, {%8,%9}, {%0,%1,%2,%3};\n"
                : "+f"(acc0), "+f"(acc1), "+f"(acc2), "+f"(acc3)
                : "r"(a[kk][0]), "r"(a[kk][1]), "r"(a[kk][2]), "r"(a[kk][3]),
                  "r"(b0), "r"(b1));
        }
        __half2 d01 = __floats2half2_rn(acc0, acc1);
        __half2 d23 = __floats2half2_rn(acc2, acc3);
        DsmW[oA * DS_STRIDE + (n0 >> 1) + lr] = *reinterpret_cast<uint32_t*>(&d01);
        DsmW[oB * DS_STRIDE + (n0 >> 1) + lr] = *reinterpret_cast<uint32_t*>(&d23);
    }
    __syncthreads();

    // phase 3: coalesced y store (fp16x2 words), 16 per thread
    __half* yb = y_scratch + (size_t)b * CH * (HH * WW);
    #pragma unroll
    for (int it = 0; it < 16; it++) {
        const int idx = it * 256 + tid;     // 0..4095
        const int o  = idx >> 6;            // channel
        const int pp = idx & 63;            // px-pair
        const int hh = h0 + (pp >> 4);
        const int wc = w0 + (pp & 15) * 2;
        const size_t off = (size_t)o * (HH * WW) + hh * WW + wc;
        *reinterpret_cast<uint32_t*>(yb + off) = DsmW[o * DS_STRIDE + pp];
    }
}

// ---------------- K2: out = x + bias + y  (pure streaming) ----------------
__global__ __launch_bounds__(256)
void k2_residual_add(const float* __restrict__ x,
                     const float* __restrict__ conv_b,
                     float* __restrict__ out) {
    const float4* x4 = reinterpret_cast<const float4*>(x);
    const uint2*  y4 = reinterpret_cast<const uint2*>(y_scratch);
    float4*       o4 = reinterpret_cast<float4*>(out);

    const int base = blockIdx.x * 1024 + threadIdx.x;
    #pragma unroll
    for (int it = 0; it < 4; it++) {
        const int idx = base + it * 256;            // float4 index
        const float4 xv = __ldcs(x4 + idx);
        const uint2  yw = __ldcs(y4 + idx);
        const __half2 y01 = *reinterpret_cast<const __half2*>(&yw.x);
        const __half2 y23 = *reinterpret_cast<const __half2*>(&yw.y);
        const float2 f01 = __half22float2(y01);
        const float2 f23 = __half22float2(y23);
        const int ch = (idx >> 12) & 63;            // (idx*4 >> 14) & 63
        const float bo = __ldg(conv_b + ch);
        float4 ov;
        ov.x = xv.x + bo + f01.x;
        ov.y = xv.y + bo + f01.y;
        ov.z = xv.z + bo + f23.x;
        ov.w = xv.w + bo + f23.y;
        __stcs(o4 + idx, ov);
    }
}

extern "C" void kernel_launch(void* const* d_in, const int* in_sizes, int n_in,
                              void* d_out, int out_size) {
    const float* x      = (const float*)d_in[0];
    const float* conv_w = (const float*)d_in[1];
    const float* conv_b = (const float*)d_in[2];
    float* out = (float*)d_out;

    dim3 g1(WW / TILE_W, HH / TILE_H, BZ);   // 4 x 32 x 32 = 4096 CTAs
    k1_mean_gemm<<<g1, 256>>>(x, conv_w);

    // 33,554,432 elems = 8,388,608 float4 = 8192 CTAs * 256 thr * 4
    k2_residual_add<<<8192, 256>>>(x, conv_b, out);
}

// round 5
// speedup vs baseline: 1.5710x; 1.5710x over previous
#include <cuda_runtime.h>
#include <cuda_fp16.h>
#include <cstdint>

#define BZ 32
#define CH 64
#define HH 128
#define WW 128
#define MP_STRIDE 264   // words per c2-plane (256 px + 8 pad)
#define WP_STRIDE 33    // words per o-row of packed weights
#define DS_STRIDE 132   // floats per o-row of staged z (128 px + 4 pad)

// dynamic smem (K1):
//   Mp   uint32_t[32*264] @ 0      (33792)  fp16x2 x pairs, [c/2][px] (2 rows x 128)
//   Wp   uint32_t[64*33]  @ 33792  (8448)   fp16x2 weights, [o][c/2]
//   DsmF float[64*132]    @ 42240  (33792)  fp32 z for current row, [o][w]
#define SMEM_BYTES 76032

// 67 MB fp16 scratch: hz[b][c][h][w] = z[w-1]+z[w]+z[w+1] (edge-clipped), z = W.x
__device__ __half hz_scratch[(size_t)BZ * CH * HH * WW];

// ---------------- K1: channel GEMM (z = W.x) + horizontal 3-sum ----------------
__global__ __launch_bounds__(256, 3)
void k1_gemm_hsum(const float* __restrict__ x,
                  const float* __restrict__ conv_w) {
    extern __shared__ unsigned char smraw[];
    uint32_t* Mp   = reinterpret_cast<uint32_t*>(smraw);
    uint32_t* Wp   = reinterpret_cast<uint32_t*>(smraw + 33792);
    float*    DsmF = reinterpret_cast<float*>(smraw + 42240);

    const int tid  = threadIdx.x;
    const int warp = tid >> 5;
    const int lane = tid & 31;

    const int b  = blockIdx.y;
    const int h0 = blockIdx.x * 2;          // 2 full-width rows per CTA

    // phase 0: weights -> fp16x2 smem
    for (int i = tid; i < 64 * 32; i += 256) {
        const int o = i >> 5, c2 = i & 31;
        const float2 wv = reinterpret_cast<const float2*>(conv_w)[o * 32 + c2];
        __half2 pk = __floats2half2_rn(wv.x, wv.y);
        Wp[o * WP_STRIDE + c2] = *reinterpret_cast<uint32_t*>(&pk);
    }

    // phase 1: load x (64 ch x 2 rows x 128 w), pack channel pairs -> Mp
    // group g covers 4 px of one channel-pair; 2048 groups, 8 per thread.
    const float* xb = x + (size_t)b * CH * HH * WW + (size_t)h0 * WW;
    #pragma unroll
    for (int it = 0; it < 8; it++) {
        const int g  = it * 256 + tid;
        const int c2 = g >> 6;              // 0..31
        const int px = (g & 63) * 4;        // 0..252
        const int row = px >> 7;            // 0 or 1
        const int w   = px & 127;
        const float4 xa = *reinterpret_cast<const float4*>(
            xb + (size_t)(2 * c2)     * (HH * WW) + row * WW + w);
        const float4 xc = *reinterpret_cast<const float4*>(
            xb + (size_t)(2 * c2 + 1) * (HH * WW) + row * WW + w);
        __half2 p0 = __floats2half2_rn(xa.x, xc.x);
        __half2 p1 = __floats2half2_rn(xa.y, xc.y);
        __half2 p2 = __floats2half2_rn(xa.z, xc.z);
        __half2 p3 = __floats2half2_rn(xa.w, xc.w);
        uint4 pk = make_uint4(*reinterpret_cast<uint32_t*>(&p0),
                              *reinterpret_cast<uint32_t*>(&p1),
                              *reinterpret_cast<uint32_t*>(&p2),
                              *reinterpret_cast<uint32_t*>(&p3));
        *reinterpret_cast<uint4*>(&Mp[c2 * MP_STRIDE + px]) = pk;
    }
    __syncthreads();

    // a-fragments (weights), loaded once
    const int o0   = (warp >> 1) * 16;
    const int nsub = (warp & 1) * 64;
    const int lq = lane >> 2;   // 0..7
    const int lr = lane & 3;    // 0..3
    uint32_t a[4][4];
    #pragma unroll
    for (int kk = 0; kk < 4; kk++) {
        a[kk][0] = Wp[(o0 + lq)     * WP_STRIDE + kk * 8 + lr];
        a[kk][1] = Wp[(o0 + 8 + lq) * WP_STRIDE + kk * 8 + lr];
        a[kk][2] = Wp[(o0 + lq)     * WP_STRIDE + kk * 8 + 4 + lr];
        a[kk][3] = Wp[(o0 + 8 + lq) * WP_STRIDE + kk * 8 + 4 + lr];
    }
    const int oA = o0 + lq, oB = oA + 8;
    __half* hzb = hz_scratch + (size_t)b * CH * (HH * WW);

    // phase 2: per full row r: GEMM (M=64,N=128,K=64) -> fp32 z smem -> h-sum -> hz
    #pragma unroll 1
    for (int r = 0; r < 2; r++) {
        const int rowbase = r * 128;
        #pragma unroll
        for (int nt = 0; nt < 8; nt++) {
            const int n0 = nsub + nt * 8;
            float acc0 = 0.f, acc1 = 0.f, acc2 = 0.f, acc3 = 0.f;
            #pragma unroll
            for (int kk = 0; kk < 4; kk++) {
                const uint32_t b0 = Mp[(kk * 8 + lr)     * MP_STRIDE + rowbase + n0 + lq];
                const uint32_t b1 = Mp[(kk * 8 + 4 + lr) * MP_STRIDE + rowbase + n0 + lq];
                asm volatile(
                    "mma.sync.aligned.m16n8k16.row.col.f32.f16.f16.f32 "
                    "{%0,%1,%2,%3}, {%4,%5,%6,%7}, {%8,%9}, {%0,%1,%2,%3};\n"
                    : "+f"(acc0), "+f"(acc1), "+f"(acc2), "+f"(acc3)
                    : "r"(a[kk][0]), "r"(a[kk][1]), "r"(a[kk][2]), "r"(a[kk][3]),
                      "r"(b0), "r"(b1));
            }
            const int p0 = n0 + lr * 2;
            *reinterpret_cast<float2*>(&DsmF[oA * DS_STRIDE + p0]) = make_float2(acc0, acc1);
            *reinterpret_cast<float2*>(&DsmF[oB * DS_STRIDE + p0]) = make_float2(acc2, acc3);
        }
        __syncthreads();

        // horizontal 3-sum (edge-clipped at w=0/127), store hz fp16x2 coalesced
        #pragma unroll
        for (int it = 0; it < 16; it++) {
            const int j = it * 256 + tid;   // 0..4095
            const int o = j >> 6;           // channel
            const int q = j & 63;           // px-pair in row
            const float* Dr = &DsmF[o * DS_STRIDE];
            const float zl = (q > 0)  ? Dr[2 * q - 1] : 0.f;
            const float z0 = Dr[2 * q];
            const float z1 = Dr[2 * q + 1];
            const float zr = (q < 63) ? Dr[2 * q + 2] : 0.f;
            __half2 hv = __floats2half2_rn(zl + z0 + z1, z0 + z1 + zr);
            *reinterpret_cast<uint32_t*>(
                hzb + (size_t)o * (HH * WW) + (h0 + r) * WW + 2 * q) =
                *reinterpret_cast<uint32_t*>(&hv);
        }
        __syncthreads();
    }
}

// ---------------- K2: vertical 3-sum + residual + bias (streaming) ----------------
__global__ __launch_bounds__(256)
void k2_vsum_residual(const float* __restrict__ x,
                      const float* __restrict__ conv_b,
                      float* __restrict__ out) {
    const float4* x4  = reinterpret_cast<const float4*>(x);
    const uint2*  hz4 = reinterpret_cast<const uint2*>(hz_scratch);
    float4*       o4  = reinterpret_cast<float4*>(out);

    const int base = blockIdx.x * 1024 + threadIdx.x;
    #pragma unroll
    for (int it = 0; it < 4; it++) {
        const int idx = base + it * 256;        // float4 / uint2 index (4 px)
        const int w4 = idx & 31;                // float4-col 0..31
        const int h  = (idx >> 5) & 127;
        const int ch = (idx >> 12) & 63;

        const float4 xv = __ldcs(x4 + idx);
        uint2 top = make_uint2(0u, 0u), bot = make_uint2(0u, 0u);
        const uint2 mid = __ldcs(hz4 + idx);
        if (h > 0)   top = __ldcs(hz4 + idx - 32);
        if (h < 127) bot = __ldcs(hz4 + idx + 32);

        const float2 t01 = __half22float2(*reinterpret_cast<const __half2*>(&top.x));
        const float2 t23 = __half22float2(*reinterpret_cast<const __half2*>(&top.y));
        const float2 m01 = __half22float2(*reinterpret_cast<const __half2*>(&mid.x));
        const float2 m23 = __half22float2(*reinterpret_cast<const __half2*>(&mid.y));
        const float2 b01 = __half22float2(*reinterpret_cast<const __half2*>(&bot.x));
        const float2 b23 = __half22float2(*reinterpret_cast<const __half2*>(&bot.y));

        const float invh = (h == 0 || h == 127) ? 0.5f : (1.0f / 3.0f);
        const float iw   = invh * (1.0f / 3.0f);
        const float iwL  = (w4 == 0)  ? invh * 0.5f : iw;   // w = 0
        const float iwR  = (w4 == 31) ? invh * 0.5f : iw;   // w = 127
        const float bo = __ldg(conv_b + ch);

        float4 ov;
        ov.x = xv.x + bo + (t01.x + m01.x + b01.x) * iwL;
        ov.y = xv.y + bo + (t01.y + m01.y + b01.y) * iw;
        ov.z = xv.z + bo + (t23.x + m23.x + b23.x) * iw;
        ov.w = xv.w + bo + (t23.y + m23.y + b23.y) * iwR;
        __stcs(o4 + idx, ov);
    }
}

extern "C" void kernel_launch(void* const* d_in, const int* in_sizes, int n_in,
                              void* d_out, int out_size) {
    const float* x      = (const float*)d_in[0];
    const float* conv_w = (const float*)d_in[1];
    const float* conv_b = (const float*)d_in[2];
    float* out = (float*)d_out;

    cudaFuncSetAttribute(k1_gemm_hsum,
                         cudaFuncAttributeMaxDynamicSharedMemorySize, SMEM_BYTES);
    dim3 g1(HH / 2, BZ);                     // 64 x 32 = 2048 CTAs
    k1_gemm_hsum<<<g1, 256, SMEM_BYTES>>>(x, conv_w);

    // 33,554,432 elems = 8,388,608 float4 = 8192 CTAs * 256 thr * 4
    k2_vsum_residual<<<8192, 256>>>(x, conv_b, out);
}

// round 6
// speedup vs baseline: 1.7267x; 1.0992x over previous
#include <cuda_runtime.h>
#include <cuda_fp16.h>
#include <cstdint>

#define BZ 32
#define CH 64
#define HH 128
#define WW 128
#define RROWS 4          // output rows per CTA
#define HW (HH * WW)
#define MPW 132          // words per c2-row of Mp (128 px + 4 pad): conflict-free
#define WP_STRIDE 33     // words per o-row of packed weights (aliased into ring slot 0)
#define ZSL 68           // words per o-row of a z ring slot (64 px-pairs + 4 pad)

// dynamic smem layout (bytes):
//   Mp    uint32_t[32*132]   @ 0      (16896)  fp16x2 x row, [c2][px]
//   ring  uint32_t[3][64*68] @ 16896  (3*17408=52224)  fp16x2 z rows
//         (Wp aliases ring slot 0 during phase 0 only)
//   BiasS float[64]          @ 69120  (256)
#define SMEM_BYTES 69376

__global__ __launch_bounds__(256, 3)
void denoise_fused(const float* __restrict__ x,
                   const float* __restrict__ conv_w,
                   const float* __restrict__ conv_b,
                   float* __restrict__ out) {
    extern __shared__ unsigned char smraw[];
    uint32_t* Mp    = reinterpret_cast<uint32_t*>(smraw);
    uint32_t* ring  = reinterpret_cast<uint32_t*>(smraw + 16896);
    uint32_t* Wp    = ring;                       // alias, consumed before ring use
    float*    BiasS = reinterpret_cast<float*>(smraw + 69120);

    const int tid  = threadIdx.x;
    const int warp = tid >> 5;
    const int lane = tid & 31;

    const int b  = blockIdx.y;
    const int h0 = blockIdx.x * RROWS;

    // ---------- phase 0: stage weights fp16x2 + bias ----------
    for (int i = tid; i < 64 * 32; i += 256) {
        const int o = i >> 5, c2 = i & 31;
        const float2 wv = reinterpret_cast<const float2*>(conv_w)[o * 32 + c2];
        __half2 pk = __floats2half2_rn(wv.x, wv.y);
        Wp[o * WP_STRIDE + c2] = *reinterpret_cast<uint32_t*>(&pk);
    }
    if (tid < 64) BiasS[tid] = conv_b[tid];
    __syncthreads();

    // a-fragments (weights) -> registers; after the next barrier Wp is dead.
    const int o0   = (warp >> 1) * 16;
    const int nsub = (warp & 1) * 64;
    const int lq = lane >> 2;   // 0..7
    const int lr = lane & 3;    // 0..3
    uint32_t a[4][4];
    #pragma unroll
    for (int kk = 0; kk < 4; kk++) {
        a[kk][0] = Wp[(o0 + lq)     * WP_STRIDE + kk * 8 + lr];
        a[kk][1] = Wp[(o0 + 8 + lq) * WP_STRIDE + kk * 8 + lr];
        a[kk][2] = Wp[(o0 + lq)     * WP_STRIDE + kk * 8 + 4 + lr];
        a[kk][3] = Wp[(o0 + 8 + lq) * WP_STRIDE + kk * 8 + 4 + lr];
    }
    const int oA = o0 + lq, oB = oA + 8;

    const float* xb = x   + (size_t)b * CH * HW;
    float*       ob = out + (size_t)b * CH * HW;

    // ---------- row pipeline: r = h0-1 .. h0+RROWS ----------
    #pragma unroll 1
    for (int r = h0 - 1; r <= h0 + RROWS; r++) {
        const int  slot  = (r + 3) % 3;
        uint32_t*  zs    = ring + slot * (64 * ZSL);
        const bool valid = (r >= 0) && (r < HH);

        // -- load x row r -> Mp (fp16x2 packed channel pairs) --
        if (valid) {
            #pragma unroll
            for (int it = 0; it < 4; it++) {
                const int g  = it * 256 + tid;      // 0..1023
                const int c2 = g >> 5;              // 0..31
                const int px = (g & 31) * 4;        // 0..124
                const float4 xa = *reinterpret_cast<const float4*>(
                    xb + (size_t)(2 * c2)     * HW + r * WW + px);
                const float4 xc = *reinterpret_cast<const float4*>(
                    xb + (size_t)(2 * c2 + 1) * HW + r * WW + px);
                __half2 p0 = __floats2half2_rn(xa.x, xc.x);
                __half2 p1 = __floats2half2_rn(xa.y, xc.y);
                __half2 p2 = __floats2half2_rn(xa.z, xc.z);
                __half2 p3 = __floats2half2_rn(xa.w, xc.w);
                uint4 pk = make_uint4(*reinterpret_cast<uint32_t*>(&p0),
                                      *reinterpret_cast<uint32_t*>(&p1),
                                      *reinterpret_cast<uint32_t*>(&p2),
                                      *reinterpret_cast<uint32_t*>(&p3));
                *reinterpret_cast<uint4*>(&Mp[c2 * MPW + px]) = pk;
            }
        }
        __syncthreads();   // Mp ready; prev iter's output phase done (slot reuse safe)

        // -- GEMM row r: z[o,p] = sum_c W[o,c]*x[c,p]  ->  ring slot (fp16x2) --
        if (valid) {
            #pragma unroll
            for (int nt = 0; nt < 8; nt++) {
                const int n0 = nsub + nt * 8;
                float acc0 = 0.f, acc1 = 0.f, acc2 = 0.f, acc3 = 0.f;
                #pragma unroll
                for (int kk = 0; kk < 4; kk++) {
                    const uint32_t b0 = Mp[(kk * 8 + lr)     * MPW + n0 + lq];
                    const uint32_t b1 = Mp[(kk * 8 + 4 + lr) * MPW + n0 + lq];
                    asm volatile(
                        "mma.sync.aligned.m16n8k16.row.col.f32.f16.f16.f32 "
                        "{%0,%1,%2,%3}, {%4,%5,%6,%7}, {%8,%9}, {%0,%1,%2,%3};\n"
                        : "+f"(acc0), "+f"(acc1), "+f"(acc2), "+f"(acc3)
                        : "r"(a[kk][0]), "r"(a[kk][1]), "r"(a[kk][2]), "r"(a[kk][3]),
                          "r"(b0), "r"(b1));
                }
                __half2 d01 = __floats2half2_rn(acc0, acc1);
                __half2 d23 = __floats2half2_rn(acc2, acc3);
                zs[oA * ZSL + (n0 >> 1) + lr] = *reinterpret_cast<uint32_t*>(&d01);
                zs[oB * ZSL + (n0 >> 1) + lr] = *reinterpret_cast<uint32_t*>(&d23);
            }
        } else {
            #pragma unroll
            for (int i = 0; i < 17; i++)        // 17*256 = 4352 = full slot
                zs[i * 256 + tid] = 0u;
        }
        __syncthreads();   // z row r ready

        // -- output row ro = r-1 : 3x3 edge-clipped mean + residual + bias --
        const int ro = r - 1;
        if (ro >= h0 && ro < h0 + RROWS) {
            const uint32_t* zt = ring + ((ro - 1 + 3) % 3) * (64 * ZSL);
            const uint32_t* zm = ring + ((ro     + 3) % 3) * (64 * ZSL);
            const uint32_t* zb = ring + ((ro + 1 + 3) % 3) * (64 * ZSL);
            const float invh = (ro == 0 || ro == HH - 1) ? 0.5f : (1.0f / 3.0f);

            #pragma unroll
            for (int it = 0; it < 16; it++) {
                const int j = it * 256 + tid;   // 0..4095
                const int o = j >> 6;           // out channel
                const int q = j & 63;           // px-pair
                const int base = o * ZSL + q;

                float csm1 = 0.f, cs0 = 0.f, cs1 = 0.f, cs2 = 0.f;
                #pragma unroll
                for (int s = 0; s < 3; s++) {
                    const uint32_t* zr = (s == 0) ? zt : (s == 1) ? zm : zb;
                    if (q > 0) {
                        uint32_t wl = zr[base - 1];
                        csm1 += __high2float(*reinterpret_cast<__half2*>(&wl));
                    }
                    uint32_t wm = zr[base];
                    const float2 m = __half22float2(*reinterpret_cast<__half2*>(&wm));
                    cs0 += m.x; cs1 += m.y;
                    if (q < 63) {
                        uint32_t wr = zr[base + 1];
                        cs2 += __low2float(*reinterpret_cast<__half2*>(&wr));
                    }
                }
                const float iwL = (q == 0)  ? 0.5f : (1.0f / 3.0f);
                const float iwR = (q == 63) ? 0.5f : (1.0f / 3.0f);
                const size_t off = (size_t)o * HW + ro * WW + 2 * q;
                const float2 xv = *reinterpret_cast<const float2*>(xb + off);
                const float bo = BiasS[o];
                float2 ov;
                ov.x = xv.x + bo + (csm1 + cs0 + cs1) * iwL * invh;
                ov.y = xv.y + bo + (cs0 + cs1 + cs2) * iwR * invh;
                __stcs(reinterpret_cast<float2*>(ob + off), ov);
            }
        }
        // next iteration's first barrier fences slot reuse
    }
}

extern "C" void kernel_launch(void* const* d_in, const int* in_sizes, int n_in,
                              void* d_out, int out_size) {
    const float* x      = (const float*)d_in[0];
    const float* conv_w = (const float*)d_in[1];
    const float* conv_b = (const float*)d_in[2];
    float* out = (float*)d_out;

    cudaFuncSetAttribute(denoise_fused,
                         cudaFuncAttributeMaxDynamicSharedMemorySize, SMEM_BYTES);
    dim3 grid(HH / RROWS, BZ);               // 32 x 32 = 1024 CTAs
    denoise_fused<<<grid, 256, SMEM_BYTES>>>(x, conv_w, conv_b, out);
}